// round 13
// baseline (speedup 1.0000x reference)
#include <cuda_runtime.h>
#include <cuda_fp16.h>
#include <math.h>
#include <stdint.h>

// ---------------- problem constants ----------------
#define BATCH 8
#define SEQT  2048
#define DIM   1024
#define M_TOT (BATCH * SEQT)          // 16384
#define NCHUNK 64
#define CHUNK_LEN (SEQT / NCHUNK)     // 32

// ---------------- scratch ----------------
__device__ __half g_pz[(size_t)M_TOT * DIM];  // z-preact (fp16)
__device__ __half g_ph[(size_t)M_TOT * DIM];  // h_tilde (fp16)
__device__ float g_Ag[BATCH * NCHUNK * DIM];
__device__ float g_Bg[BATCH * NCHUNK * DIM];
__device__ float g_cr[BATCH * NCHUNK * DIM];
__device__ __half g_Xh[(size_t)M_TOT * DIM];            // fp16 X
__device__ __half g_Wt[(size_t)2048 * DIM];             // row n (0..1023 Wz^T, 1024..2047 Wh^T)

// ---------------- MUFU sigmoid ----------------
__device__ __forceinline__ float sigmoid_mufu(float x) {
    const float LOG2E = 1.4426950408889634f;
    float e;
    asm("ex2.approx.f32 %0, %1;" : "=f"(e) : "f"(-x * LOG2E));
    float r;
    asm("rcp.approx.f32 %0, %1;" : "=f"(r) : "f"(1.0f + e));
    return r;
}

// ---------------- PTX helpers ----------------
__device__ __forceinline__ uint32_t smem_u32(const void* p) {
    uint32_t a;
    asm("{ .reg .u64 t; cvta.to.shared.u64 t, %1; cvt.u32.u64 %0, t; }" : "=r"(a) : "l"(p));
    return a;
}
__device__ __forceinline__ void cp16(uint32_t dst, const void* src) {
    asm volatile("cp.async.cg.shared.global [%0], [%1], 16;" :: "r"(dst), "l"(src) : "memory");
}
__device__ __forceinline__ void ldsm4(uint32_t* r, uint32_t addr) {
    asm volatile("ldmatrix.sync.aligned.m8n8.x4.shared.b16 {%0,%1,%2,%3}, [%4];"
                 : "=r"(r[0]), "=r"(r[1]), "=r"(r[2]), "=r"(r[3]) : "r"(addr));
}
__device__ __forceinline__ void mma_f16(float* d, const uint32_t* a, const uint32_t* b) {
    asm volatile(
        "mma.sync.aligned.m16n8k16.row.col.f32.f16.f16.f32 "
        "{%0,%1,%2,%3}, {%4,%5,%6,%7}, {%8,%9}, {%0,%1,%2,%3};"
        : "+f"(d[0]), "+f"(d[1]), "+f"(d[2]), "+f"(d[3])
        : "r"(a[0]), "r"(a[1]), "r"(a[2]), "r"(a[3]), "r"(b[0]), "r"(b[1]));
}

// ---------------- preprocess: X -> fp16 ----------------
__global__ __launch_bounds__(256) void convx_kernel(const float* __restrict__ X)
{
    const int t = blockIdx.x * 256 + threadIdx.x;
    const float4 v = ((const float4*)X)[t];
    __half2 p0 = __floats2half2_rn(v.x, v.y);
    __half2 p1 = __floats2half2_rn(v.z, v.w);
    uint2 o;
    o.x = *(uint32_t*)&p0;
    o.y = *(uint32_t*)&p1;
    ((uint2*)g_Xh)[t] = o;
}

// ---------------- preprocess: W transpose -> fp16 ----------------
__global__ __launch_bounds__(256) void convw_kernel(const float* __restrict__ Wz,
                                                    const float* __restrict__ Wh)
{
    __shared__ float tile[32][33];
    const int zz = blockIdx.z;
    const float* __restrict__ W = zz ? Wh : Wz;
    const int k0 = blockIdx.x * 32;
    const int n0 = blockIdx.y * 32;
    const int tx = threadIdx.x;
    const int ty = threadIdx.y;
    #pragma unroll
    for (int i = 0; i < 4; i++)
        tile[ty + 8 * i][tx] = W[(size_t)(k0 + ty + 8 * i) * 1024 + n0 + tx];
    __syncthreads();
    #pragma unroll
    for (int i = 0; i < 4; i++) {
        const int n = n0 + ty + 8 * i;
        g_Wt[(size_t)(zz * 1024 + n) * 1024 + k0 + tx] = __float2half_rn(tile[tx][ty + 8 * i]);
    }
}

// ---------------- HMMA dual GEMM, 8 warps, ks-register-double-buffered ----------
#define BM 128
#define BN 256
#define NK 16
#define NSTAGE 4
#define A_BYTES (128 * 128)                 // 16 KB
#define B_BYTES (256 * 128)                 // 32 KB
#define STAGE_BYTES (A_BYTES + B_BYTES)     // 48 KB
#define OFF_BIAS (NSTAGE * STAGE_BYTES)     // 196608
#define GEMM_SMEM (OFF_BIAS + 1024)

__global__ __launch_bounds__(256, 1) void gemm_hmma_kernel(
    const float* __restrict__ bz, const float* __restrict__ bh)
{
    extern __shared__ char smem[];
    const uint32_t sb = smem_u32(smem);
    const int tid  = threadIdx.x;
    const int wid  = tid >> 5;
    const int lane = tid & 31;
    const int n0 = blockIdx.x * BN;
    const int m0 = blockIdx.y * BM;

    const bool isZ = (n0 < 1024);
    const int ncol = n0 & 1023;

    {
        const float* __restrict__ bias = isZ ? bz : bh;
        ((float*)(smem + OFF_BIAS))[tid] = bias[ncol + tid];
    }

    const int wm = wid & 1;
    const int wn = wid >> 1;

    const int a_row  = wm * 64 + (lane & 15);
    const uint32_t a_xor  = (uint32_t)((a_row & 7) << 4);
    const uint32_t a_half = (uint32_t)((lane >> 4) * 16);
    const int b_row  = wn * 64 + ((lane >> 3) & 1) * 8 + (lane & 7);
    const uint32_t b_xor  = (uint32_t)((b_row & 7) << 4);
    const uint32_t b_half = (uint32_t)((lane >> 4) * 16);

    float acc[4][8][4];
    #pragma unroll
    for (int i = 0; i < 4; i++)
        #pragma unroll
        for (int j = 0; j < 8; j++)
            #pragma unroll
            for (int q = 0; q < 4; q++) acc[i][j][q] = 0.0f;

    auto load_chunk = [&](int kc) {
        const uint32_t stb = sb + (uint32_t)((kc & (NSTAGE - 1)) * STAGE_BYTES);
        const int k0 = kc << 6;
        #pragma unroll
        for (int i = 0; i < 4; i++) {
            const int idx = tid + 256 * i;
            const int r = idx >> 3, g = idx & 7;
            const void* src = &g_Xh[(size_t)(m0 + r) * 1024 + k0 + g * 8];
            cp16(stb + (uint32_t)(r * 128 + ((g * 16) ^ ((r & 7) << 4))), src);
        }
        #pragma unroll
        for (int i = 0; i < 8; i++) {
            const int idx = tid + 256 * i;
            const int r = idx >> 3, g = idx & 7;
            const void* src = &g_Wt[(size_t)(n0 + r) * 1024 + k0 + g * 8];
            cp16(stb + A_BYTES + (uint32_t)(r * 128 + ((g * 16) ^ ((r & 7) << 4))), src);
        }
        asm volatile("cp.async.commit_group;" ::: "memory");
    };

    uint32_t afr[2][4][4];
    uint32_t bfr[2][8][2];

    auto load_frags = [&](uint32_t stb, int ks, int buf) {
        const uint32_t kbase = (uint32_t)(ks * 32);
        #pragma unroll
        for (int mt = 0; mt < 4; mt++) {
            const uint32_t addr = stb + (uint32_t)((a_row + mt * 16) * 128)
                                + ((kbase + a_half) ^ a_xor);
            ldsm4(afr[buf][mt], addr);
        }
        #pragma unroll
        for (int p = 0; p < 4; p++) {
            uint32_t r4[4];
            const uint32_t addr = stb + A_BYTES + (uint32_t)((b_row + p * 16) * 128)
                                + ((kbase + b_half) ^ b_xor);
            ldsm4(r4, addr);
            bfr[buf][2 * p + 0][0] = r4[0]; bfr[buf][2 * p + 0][1] = r4[2];
            bfr[buf][2 * p + 1][0] = r4[1]; bfr[buf][2 * p + 1][1] = r4[3];
        }
    };

    load_chunk(0);
    load_chunk(1);
    load_chunk(2);

    for (int kc = 0; kc < NK; kc++) {
        if (kc + 2 < NK)      asm volatile("cp.async.wait_group 2;" ::: "memory");
        else if (kc + 1 < NK) asm volatile("cp.async.wait_group 1;" ::: "memory");
        else                  asm volatile("cp.async.wait_group 0;" ::: "memory");
        __syncthreads();

        if (kc + 3 < NK) load_chunk(kc + 3);

        const uint32_t stb = sb + (uint32_t)((kc & (NSTAGE - 1)) * STAGE_BYTES);
        load_frags(stb, 0, 0);
        #pragma unroll
        for (int ks = 0; ks < 4; ks++) {
            const int cur = ks & 1;
            if (ks < 3) load_frags(stb, ks + 1, cur ^ 1);
            #pragma unroll
            for (int mt = 0; mt < 4; mt++)
                #pragma unroll
                for (int nt = 0; nt < 8; nt++)
                    mma_f16(acc[mt][nt], afr[cur][mt], bfr[cur][nt]);
        }
    }

    // epilogue: bias + fp16 store
    const float* sh_bias = (const float*)(smem + OFF_BIAS);
    __half* __restrict__ outp = isZ ? g_pz : g_ph;
    const int quad = lane >> 2;
    const int tq   = lane & 3;

    #pragma unroll
    for (int mt = 0; mt < 4; mt++) {
        const int row = m0 + wm * 64 + mt * 16 + quad;
        #pragma unroll
        for (int nt = 0; nt < 8; nt++) {
            const int cloc = wn * 64 + nt * 8 + tq * 2;
            const float b0 = sh_bias[cloc];
            const float b1 = sh_bias[cloc + 1];
            __half2 h01 = __floats2half2_rn(acc[mt][nt][0] + b0, acc[mt][nt][1] + b1);
            __half2 h23 = __floats2half2_rn(acc[mt][nt][2] + b0, acc[mt][nt][3] + b1);
            *(__half2*)(outp + (size_t)row * 1024 + ncol + cloc)       = h01;
            *(__half2*)(outp + (size_t)(row + 8) * 1024 + ncol + cloc) = h23;
        }
    }
}

// ---------------- chunked scan: pass 1 (4 d-lanes per thread) ----------------
__global__ __launch_bounds__(256) void scan_partial_kernel()
{
    const int g  = blockIdx.x * 256 + threadIdx.x;     // quad index
    const int dq = g & 255;                            // d-quad (d = 4*dq)
    const int bc = g >> 8;

    const int c  = bc & (NCHUNK - 1);
    const int b  = bc >> 6;

    const size_t base = ((size_t)(b * SEQT + c * CHUNK_LEN)) * DIM + dq * 4;
    float A0 = 1.0f, B0 = 0.0f, A1 = 1.0f, B1 = 0.0f;
    float A2 = 1.0f, B2 = 0.0f, A3 = 1.0f, B3 = 0.0f;
    #pragma unroll 8
    for (int t = 0; t < CHUNK_LEN; t++) {
        const size_t idx = base + (size_t)t * DIM;
        const uint2 zr = *(const uint2*)(g_pz + idx);
        const uint2 hr = *(const uint2*)(g_ph + idx);
        const float2 z01 = __half22float2(*(const __half2*)&zr.x);
        const float2 z23 = __half22float2(*(const __half2*)&zr.y);
        const float2 h01 = __half22float2(*(const __half2*)&hr.x);
        const float2 h23 = __half22float2(*(const __half2*)&hr.y);
        const float s0 = sigmoid_mufu(z01.x);
        const float s1 = sigmoid_mufu(z01.y);
        const float s2 = sigmoid_mufu(z23.x);
        const float s3 = sigmoid_mufu(z23.y);
        B0 = fmaf(1.0f - s0, B0, s0 * h01.x);  A0 *= (1.0f - s0);
        B1 = fmaf(1.0f - s1, B1, s1 * h01.y);  A1 *= (1.0f - s1);
        B2 = fmaf(1.0f - s2, B2, s2 * h23.x);  A2 *= (1.0f - s2);
        B3 = fmaf(1.0f - s3, B3, s3 * h23.y);  A3 *= (1.0f - s3);
    }
    *(float4*)(g_Ag + (size_t)bc * DIM + dq * 4) = make_float4(A0, A1, A2, A3);
    *(float4*)(g_Bg + (size_t)bc * DIM + dq * 4) = make_float4(B0, B1, B2, B3);
}

// ---------------- chunked scan: pass 2 ----------------
__global__ __launch_bounds__(256) void scan_carry_kernel()
{
    const int g = blockIdx.x * 256 + threadIdx.x;
    const int d = g & (DIM - 1);
    const int b = g >> 10;

    float h = 0.0f;
    #pragma unroll
    for (int c = 0; c < NCHUNK; c++) {
        const int idx = (b * NCHUNK + c) * DIM + d;
        g_cr[idx] = h;
        h = fmaf(g_Ag[idx], h, g_Bg[idx]);
    }
}

// ---------------- fused scan pass 3 + Swish + LayerNorm (4 t per round) ---------
__global__ __launch_bounds__(1024) void sfln_kernel(
    const float* __restrict__ beta_ptr,
    const float* __restrict__ gamma, const float* __restrict__ lbeta,
    float* __restrict__ out)
{
    __shared__ float2 red[4][32];
    __shared__ float2 tot[4];

    const int d  = threadIdx.x;
    const int bc = blockIdx.x;
    const int c  = bc & (NCHUNK - 1);
    const int b  = bc >> 6;
    const int lane = d & 31;
    const int wrp  = d >> 5;

    const float beta = *beta_ptr;
    const float gm = gamma[d];
    const float bt = lbeta[d];

    const size_t base = ((size_t)(b * SEQT + c * CHUNK_LEN)) * DIM + d;
    float h = g_cr[bc * DIM + d];

    for (int t0 = 0; t0 < CHUNK_LEN; t0 += 4) {
        float y[4];
        #pragma unroll
        for (int tt = 0; tt < 4; tt++) {
            const size_t idx = base + (size_t)(t0 + tt) * DIM;
            const float z  = __half2float(g_pz[idx]);
            const float ht = __half2float(g_ph[idx]);
            const float s  = sigmoid_mufu(z);
            h = fmaf(1.0f - s, h, s * ht);
            const float sw = beta * h;
            y[tt] = sw * sigmoid_mufu(sw);
        }
        #pragma unroll
        for (int tt = 0; tt < 4; tt++) {
            float s1 = y[tt], s2 = y[tt] * y[tt];
            #pragma unroll
            for (int o = 16; o > 0; o >>= 1) {
                s1 += __shfl_xor_sync(0xffffffffu, s1, o);
                s2 += __shfl_xor_sync(0xffffffffu, s2, o);
            }
            if (lane == 0) red[tt][wrp] = make_float2(s1, s2);
        }
        __syncthreads();
        if (wrp < 4) {
            float2 v = red[wrp][lane];
            #pragma unroll
            for (int o = 16; o > 0; o >>= 1) {
                v.x += __shfl_xor_sync(0xffffffffu, v.x, o);
                v.y += __shfl_xor_sync(0xffffffffu, v.y, o);
            }
            if (lane == 0) tot[wrp] = v;
        }
        __syncthreads();
        #pragma unroll
        for (int tt = 0; tt < 4; tt++) {
            const float2 T = tot[tt];
            const float mu  = T.x * (1.0f / 1024.0f);
            const float var = fmaf(T.y, 1.0f / 1024.0f, -mu * mu);
            const float rs  = rsqrtf(var + 1e-5f);
            out[base + (size_t)(t0 + tt) * DIM] = (y[tt] - mu) * rs * gm + bt;
        }
    }
}

// ---------------- launch ----------------
extern "C" void kernel_launch(void* const* d_in, const int* in_sizes, int n_in,
                              void* d_out, int out_size)
{
    const float* x     = (const float*)d_in[0];
    const float* Wz    = (const float*)d_in[1];
    const float* bz    = (const float*)d_in[2];
    const float* Wh    = (const float*)d_in[3];
    const float* bh    = (const float*)d_in[4];
    const float* sbeta = (const float*)d_in[5];
    const float* gamma = (const float*)d_in[6];
    const float* lbeta = (const float*)d_in[7];
    float* out = (float*)d_out;

    convx_kernel<<<(M_TOT * DIM / 4) / 256, 256>>>(x);
    dim3 wgrid(32, 32, 2);
    convw_kernel<<<wgrid, dim3(32, 8)>>>(Wz, Wh);

    cudaFuncSetAttribute(gemm_hmma_kernel, cudaFuncAttributeMaxDynamicSharedMemorySize, GEMM_SMEM);
    gemm_hmma_kernel<<<dim3(2048 / BN, M_TOT / BM), 256, GEMM_SMEM>>>(bz, bh);

    scan_partial_kernel<<<(BATCH * NCHUNK * DIM / 4) / 256, 256>>>();
    scan_carry_kernel<<<(BATCH * DIM) / 256, 256>>>();
    sfln_kernel<<<BATCH * NCHUNK, 1024>>>(sbeta, gamma, lbeta, out);
}

// round 14
// speedup vs baseline: 1.0350x; 1.0350x over previous
#include <cuda_runtime.h>
#include <cuda_fp16.h>
#include <math.h>
#include <stdint.h>

// ---------------- problem constants ----------------
#define BATCH 8
#define SEQT  2048
#define DIM   1024
#define M_TOT (BATCH * SEQT)          // 16384
#define NCHUNK 64
#define CHUNK_LEN (SEQT / NCHUNK)     // 32

// ---------------- scratch ----------------
__device__ __half g_pz[(size_t)M_TOT * DIM];  // z-preact (fp16)
__device__ __half g_ph[(size_t)M_TOT * DIM];  // h_tilde (fp16)
__device__ float g_Ag[BATCH * NCHUNK * DIM];
__device__ float g_Bg[BATCH * NCHUNK * DIM];
__device__ float g_cr[BATCH * NCHUNK * DIM];
__device__ __half g_Xh[(size_t)M_TOT * DIM];            // fp16 X
__device__ __half g_Wt[(size_t)2048 * DIM];             // row n (0..1023 Wz^T, 1024..2047 Wh^T)

// ---------------- sigmoid via tanh.approx (1 MUFU) ----------------
__device__ __forceinline__ float sigmoid_tanh(float x) {
    float t;
    asm("tanh.approx.f32 %0, %1;" : "=f"(t) : "f"(0.5f * x));
    return fmaf(0.5f, t, 0.5f);
}

// ---------------- PTX helpers ----------------
__device__ __forceinline__ uint32_t smem_u32(const void* p) {
    uint32_t a;
    asm("{ .reg .u64 t; cvta.to.shared.u64 t, %1; cvt.u32.u64 %0, t; }" : "=r"(a) : "l"(p));
    return a;
}
__device__ __forceinline__ void cp16(uint32_t dst, const void* src) {
    asm volatile("cp.async.cg.shared.global [%0], [%1], 16;" :: "r"(dst), "l"(src) : "memory");
}
__device__ __forceinline__ void ldsm4(uint32_t* r, uint32_t addr) {
    asm volatile("ldmatrix.sync.aligned.m8n8.x4.shared.b16 {%0,%1,%2,%3}, [%4];"
                 : "=r"(r[0]), "=r"(r[1]), "=r"(r[2]), "=r"(r[3]) : "r"(addr));
}
__device__ __forceinline__ void mma_f16(float* d, const uint32_t* a, const uint32_t* b) {
    asm volatile(
        "mma.sync.aligned.m16n8k16.row.col.f32.f16.f16.f32 "
        "{%0,%1,%2,%3}, {%4,%5,%6,%7}, {%8,%9}, {%0,%1,%2,%3};"
        : "+f"(d[0]), "+f"(d[1]), "+f"(d[2]), "+f"(d[3])
        : "r"(a[0]), "r"(a[1]), "r"(a[2]), "r"(a[3]), "r"(b[0]), "r"(b[1]));
}

// ---------------- preprocess: X -> fp16 ----------------
__global__ __launch_bounds__(256) void convx_kernel(const float* __restrict__ X)
{
    const int t = blockIdx.x * 256 + threadIdx.x;
    const float4 v = ((const float4*)X)[t];
    __half2 p0 = __floats2half2_rn(v.x, v.y);
    __half2 p1 = __floats2half2_rn(v.z, v.w);
    uint2 o;
    o.x = *(uint32_t*)&p0;
    o.y = *(uint32_t*)&p1;
    ((uint2*)g_Xh)[t] = o;
}

// ---------------- preprocess: W transpose -> fp16 ----------------
__global__ __launch_bounds__(256) void convw_kernel(const float* __restrict__ Wz,
                                                    const float* __restrict__ Wh)
{
    __shared__ float tile[32][33];
    const int zz = blockIdx.z;
    const float* __restrict__ W = zz ? Wh : Wz;
    const int k0 = blockIdx.x * 32;
    const int n0 = blockIdx.y * 32;
    const int tx = threadIdx.x;
    const int ty = threadIdx.y;
    #pragma unroll
    for (int i = 0; i < 4; i++)
        tile[ty + 8 * i][tx] = W[(size_t)(k0 + ty + 8 * i) * 1024 + n0 + tx];
    __syncthreads();
    #pragma unroll
    for (int i = 0; i < 4; i++) {
        const int n = n0 + ty + 8 * i;
        g_Wt[(size_t)(zz * 1024 + n) * 1024 + k0 + tx] = __float2half_rn(tile[tx][ty + 8 * i]);
    }
}

// ---------------- HMMA dual GEMM (fp16 in, fp32 accum), 8 warps, fp16 out -------
#define BM 128
#define BN 256
#define NK 16
#define NSTAGE 4
#define A_BYTES (128 * 128)                 // 16 KB
#define B_BYTES (256 * 128)                 // 32 KB
#define STAGE_BYTES (A_BYTES + B_BYTES)     // 48 KB
#define OFF_BIAS (NSTAGE * STAGE_BYTES)     // 196608
#define GEMM_SMEM (OFF_BIAS + 1024)

__global__ __launch_bounds__(256, 1) void gemm_hmma_kernel(
    const float* __restrict__ bz, const float* __restrict__ bh)
{
    extern __shared__ char smem[];
    const uint32_t sb = smem_u32(smem);
    const int tid  = threadIdx.x;
    const int wid  = tid >> 5;
    const int lane = tid & 31;
    const int n0 = blockIdx.x * BN;
    const int m0 = blockIdx.y * BM;

    const bool isZ = (n0 < 1024);
    const int ncol = n0 & 1023;

    {
        const float* __restrict__ bias = isZ ? bz : bh;
        ((float*)(smem + OFF_BIAS))[tid] = bias[ncol + tid];
    }

    const int wm = wid & 1;
    const int wn = wid >> 1;

    const int a_row  = wm * 64 + (lane & 15);
    const uint32_t a_xor  = (uint32_t)((a_row & 7) << 4);
    const uint32_t a_half = (uint32_t)((lane >> 4) * 16);
    const int b_row  = wn * 64 + ((lane >> 3) & 1) * 8 + (lane & 7);
    const uint32_t b_xor  = (uint32_t)((b_row & 7) << 4);
    const uint32_t b_half = (uint32_t)((lane >> 4) * 16);

    float acc[4][8][4];
    #pragma unroll
    for (int i = 0; i < 4; i++)
        #pragma unroll
        for (int j = 0; j < 8; j++)
            #pragma unroll
            for (int q = 0; q < 4; q++) acc[i][j][q] = 0.0f;

    auto load_chunk = [&](int kc) {
        const uint32_t stb = sb + (uint32_t)((kc & (NSTAGE - 1)) * STAGE_BYTES);
        const int k0 = kc << 6;
        #pragma unroll
        for (int i = 0; i < 4; i++) {
            const int idx = tid + 256 * i;
            const int r = idx >> 3, g = idx & 7;
            const void* src = &g_Xh[(size_t)(m0 + r) * 1024 + k0 + g * 8];
            cp16(stb + (uint32_t)(r * 128 + ((g * 16) ^ ((r & 7) << 4))), src);
        }
        #pragma unroll
        for (int i = 0; i < 8; i++) {
            const int idx = tid + 256 * i;
            const int r = idx >> 3, g = idx & 7;
            const void* src = &g_Wt[(size_t)(n0 + r) * 1024 + k0 + g * 8];
            cp16(stb + A_BYTES + (uint32_t)(r * 128 + ((g * 16) ^ ((r & 7) << 4))), src);
        }
        asm volatile("cp.async.commit_group;" ::: "memory");
    };

    load_chunk(0);
    load_chunk(1);
    load_chunk(2);

    for (int kc = 0; kc < NK; kc++) {
        if (kc + 2 < NK)      asm volatile("cp.async.wait_group 2;" ::: "memory");
        else if (kc + 1 < NK) asm volatile("cp.async.wait_group 1;" ::: "memory");
        else                  asm volatile("cp.async.wait_group 0;" ::: "memory");
        __syncthreads();

        if (kc + 3 < NK) load_chunk(kc + 3);

        const uint32_t stb = sb + (uint32_t)((kc & (NSTAGE - 1)) * STAGE_BYTES);
        #pragma unroll
        for (int ks = 0; ks < 4; ks++) {
            uint32_t afr[4][4];
            uint32_t bfr[8][2];
            const uint32_t kbase = (uint32_t)(ks * 32);
            #pragma unroll
            for (int mt = 0; mt < 4; mt++) {
                const uint32_t addr = stb + (uint32_t)((a_row + mt * 16) * 128)
                                    + ((kbase + a_half) ^ a_xor);
                ldsm4(afr[mt], addr);
            }
            #pragma unroll
            for (int p = 0; p < 4; p++) {
                uint32_t r4[4];
                const uint32_t addr = stb + A_BYTES + (uint32_t)((b_row + p * 16) * 128)
                                    + ((kbase + b_half) ^ b_xor);
                ldsm4(r4, addr);
                bfr[2 * p + 0][0] = r4[0]; bfr[2 * p + 0][1] = r4[2];
                bfr[2 * p + 1][0] = r4[1]; bfr[2 * p + 1][1] = r4[3];
            }
            #pragma unroll
            for (int mt = 0; mt < 4; mt++)
                #pragma unroll
                for (int nt = 0; nt < 8; nt++)
                    mma_f16(acc[mt][nt], afr[mt], bfr[nt]);
        }
    }

    // epilogue: bias + fp16 store
    const float* sh_bias = (const float*)(smem + OFF_BIAS);
    __half* __restrict__ outp = isZ ? g_pz : g_ph;
    const int quad = lane >> 2;
    const int tq   = lane & 3;

    #pragma unroll
    for (int mt = 0; mt < 4; mt++) {
        const int row = m0 + wm * 64 + mt * 16 + quad;
        #pragma unroll
        for (int nt = 0; nt < 8; nt++) {
            const int cloc = wn * 64 + nt * 8 + tq * 2;
            const float b0 = sh_bias[cloc];
            const float b1 = sh_bias[cloc + 1];
            __half2 h01 = __floats2half2_rn(acc[mt][nt][0] + b0, acc[mt][nt][1] + b1);
            __half2 h23 = __floats2half2_rn(acc[mt][nt][2] + b0, acc[mt][nt][3] + b1);
            *(__half2*)(outp + (size_t)row * 1024 + ncol + cloc)       = h01;
            *(__half2*)(outp + (size_t)(row + 8) * 1024 + ncol + cloc) = h23;
        }
    }
}

// ---------------- chunked scan: pass 1 (2 d-lanes per thread) ----------------
__global__ __launch_bounds__(256) void scan_partial_kernel()
{
    const int g  = blockIdx.x * 256 + threadIdx.x;     // pair index
    const int dp = g & 511;                            // d-pair (d = 2*dp)
    const int bc = g >> 9;
    const int c  = bc & (NCHUNK - 1);
    const int b  = bc >> 6;

    const size_t base = ((size_t)(b * SEQT + c * CHUNK_LEN)) * DIM + dp * 2;
    float A0 = 1.0f, B0 = 0.0f, A1 = 1.0f, B1 = 0.0f;
    #pragma unroll 8
    for (int t = 0; t < CHUNK_LEN; t++) {
        const size_t idx = base + (size_t)t * DIM;
        const float2 zf = __half22float2(*(const __half2*)(g_pz + idx));
        const float2 hf = __half22float2(*(const __half2*)(g_ph + idx));
        const float s0 = sigmoid_tanh(zf.x);
        const float s1 = sigmoid_tanh(zf.y);
        const float a0 = 1.0f - s0;
        const float a1 = 1.0f - s1;
        B0 = fmaf(a0, B0, s0 * hf.x);  A0 *= a0;
        B1 = fmaf(a1, B1, s1 * hf.y);  A1 *= a1;
    }
    *(float2*)(g_Ag + bc * DIM + dp * 2) = make_float2(A0, A1);
    *(float2*)(g_Bg + bc * DIM + dp * 2) = make_float2(B0, B1);
}

// ---------------- chunked scan: pass 2 ----------------
__global__ __launch_bounds__(256) void scan_carry_kernel()
{
    const int g = blockIdx.x * 256 + threadIdx.x;
    const int d = g & (DIM - 1);
    const int b = g >> 10;

    float h = 0.0f;
    #pragma unroll
    for (int c = 0; c < NCHUNK; c++) {
        const int idx = (b * NCHUNK + c) * DIM + d;
        g_cr[idx] = h;
        h = fmaf(g_Ag[idx], h, g_Bg[idx]);
    }
}

// ---------------- fused scan pass 3 + Swish + LayerNorm (8 t per round) ---------
__global__ __launch_bounds__(1024) void sfln_kernel(
    const float* __restrict__ beta_ptr,
    const float* __restrict__ gamma, const float* __restrict__ lbeta,
    float* __restrict__ out)
{
    __shared__ float2 red[8][32];
    __shared__ float2 tot[8];

    const int d  = threadIdx.x;
    const int bc = blockIdx.x;
    const int c  = bc & (NCHUNK - 1);
    const int b  = bc >> 6;
    const int lane = d & 31;
    const int wrp  = d >> 5;

    const float beta = *beta_ptr;
    const float gm = gamma[d];
    const float bt = lbeta[d];

    const size_t base = ((size_t)(b * SEQT + c * CHUNK_LEN)) * DIM + d;
    float h = g_cr[bc * DIM + d];

    for (int t0 = 0; t0 < CHUNK_LEN; t0 += 8) {
        float y[8];
        #pragma unroll
        for (int tt = 0; tt < 8; tt++) {
            const size_t idx = base + (size_t)(t0 + tt) * DIM;
            const float z  = __half2float(g_pz[idx]);
            const float ht = __half2float(g_ph[idx]);
            const float s  = sigmoid_tanh(z);
            h = fmaf(1.0f - s, h, s * ht);
            const float sw = beta * h;
            y[tt] = sw * sigmoid_tanh(sw);
        }
        #pragma unroll
        for (int tt = 0; tt < 8; tt++) {
            float s1 = y[tt], s2 = y[tt] * y[tt];
            #pragma unroll
            for (int o = 16; o > 0; o >>= 1) {
                s1 += __shfl_xor_sync(0xffffffffu, s1, o);
                s2 += __shfl_xor_sync(0xffffffffu, s2, o);
            }
            if (lane == 0) red[tt][wrp] = make_float2(s1, s2);
        }
        __syncthreads();
        if (wrp < 8) {
            float2 v = red[wrp][lane];
            #pragma unroll
            for (int o = 16; o > 0; o >>= 1) {
                v.x += __shfl_xor_sync(0xffffffffu, v.x, o);
                v.y += __shfl_xor_sync(0xffffffffu, v.y, o);
            }
            if (lane == 0) tot[wrp] = v;
        }
        __syncthreads();
        #pragma unroll
        for (int tt = 0; tt < 8; tt++) {
            const float2 T = tot[tt];
            const float mu  = T.x * (1.0f / 1024.0f);
            const float var = fmaf(T.y, 1.0f / 1024.0f, -mu * mu);
            const float rs  = rsqrtf(var + 1e-5f);
            out[base + (size_t)(t0 + tt) * DIM] = (y[tt] - mu) * rs * gm + bt;
        }
    }
}

// ---------------- launch ----------------
extern "C" void kernel_launch(void* const* d_in, const int* in_sizes, int n_in,
                              void* d_out, int out_size)
{
    const float* x     = (const float*)d_in[0];
    const float* Wz    = (const float*)d_in[1];
    const float* bz    = (const float*)d_in[2];
    const float* Wh    = (const float*)d_in[3];
    const float* bh    = (const float*)d_in[4];
    const float* sbeta = (const float*)d_in[5];
    const float* gamma = (const float*)d_in[6];
    const float* lbeta = (const float*)d_in[7];
    float* out = (float*)d_out;

    convx_kernel<<<(M_TOT * DIM / 4) / 256, 256>>>(x);
    dim3 wgrid(32, 32, 2);
    convw_kernel<<<wgrid, dim3(32, 8)>>>(Wz, Wh);

    cudaFuncSetAttribute(gemm_hmma_kernel, cudaFuncAttributeMaxDynamicSharedMemorySize, GEMM_SMEM);
    gemm_hmma_kernel<<<dim3(2048 / BN, M_TOT / BM), 256, GEMM_SMEM>>>(bz, bh);

    scan_partial_kernel<<<(BATCH * NCHUNK * DIM / 2) / 256, 256>>>();
    scan_carry_kernel<<<(BATCH * DIM) / 256, 256>>>();
    sfln_kernel<<<BATCH * NCHUNK, 1024>>>(sbeta, gamma, lbeta, out);
}

// round 15
// speedup vs baseline: 1.0489x; 1.0135x over previous
#include <cuda_runtime.h>
#include <cuda_fp16.h>
#include <math.h>
#include <stdint.h>

// ---------------- problem constants ----------------
#define BATCH 8
#define SEQT  2048
#define DIM   1024
#define M_TOT (BATCH * SEQT)          // 16384
#define NCHUNK 64
#define CHUNK_LEN (SEQT / NCHUNK)     // 32

// ---------------- scratch ----------------
__device__ __half g_pz[(size_t)M_TOT * DIM];  // z-preact (fp16)
__device__ __half g_ph[(size_t)M_TOT * DIM];  // h_tilde (fp16)
__device__ float g_Ag[BATCH * NCHUNK * DIM];
__device__ float g_Bg[BATCH * NCHUNK * DIM];
__device__ float g_cr[BATCH * NCHUNK * DIM];
__device__ __half g_Xh[(size_t)M_TOT * DIM];            // fp16 X
__device__ __half g_Wt[(size_t)2048 * DIM];             // row n (0..1023 Wz^T, 1024..2047 Wh^T)

// ---------------- sigmoid via tanh.approx (1 MUFU) ----------------
__device__ __forceinline__ float sigmoid_tanh(float x) {
    float t;
    asm("tanh.approx.f32 %0, %1;" : "=f"(t) : "f"(0.5f * x));
    return fmaf(0.5f, t, 0.5f);
}

// ---------------- PTX helpers ----------------
__device__ __forceinline__ uint32_t smem_u32(const void* p) {
    uint32_t a;
    asm("{ .reg .u64 t; cvta.to.shared.u64 t, %1; cvt.u32.u64 %0, t; }" : "=r"(a) : "l"(p));
    return a;
}
__device__ __forceinline__ void cp16(uint32_t dst, const void* src) {
    asm volatile("cp.async.cg.shared.global [%0], [%1], 16;" :: "r"(dst), "l"(src) : "memory");
}
__device__ __forceinline__ void ldsm4(uint32_t* r, uint32_t addr) {
    asm volatile("ldmatrix.sync.aligned.m8n8.x4.shared.b16 {%0,%1,%2,%3}, [%4];"
                 : "=r"(r[0]), "=r"(r[1]), "=r"(r[2]), "=r"(r[3]) : "r"(addr));
}
__device__ __forceinline__ void mma_f16(float* d, const uint32_t* a, const uint32_t* b) {
    asm volatile(
        "mma.sync.aligned.m16n8k16.row.col.f32.f16.f16.f32 "
        "{%0,%1,%2,%3}, {%4,%5,%6,%7}, {%8,%9}, {%0,%1,%2,%3};"
        : "+f"(d[0]), "+f"(d[1]), "+f"(d[2]), "+f"(d[3])
        : "r"(a[0]), "r"(a[1]), "r"(a[2]), "r"(a[3]), "r"(b[0]), "r"(b[1]));
}

// ---------------- preprocess: X -> fp16 ----------------
__global__ __launch_bounds__(256) void convx_kernel(const float* __restrict__ X)
{
    const int t = blockIdx.x * 256 + threadIdx.x;
    const float4 v = ((const float4*)X)[t];
    __half2 p0 = __floats2half2_rn(v.x, v.y);
    __half2 p1 = __floats2half2_rn(v.z, v.w);
    uint2 o;
    o.x = *(uint32_t*)&p0;
    o.y = *(uint32_t*)&p1;
    ((uint2*)g_Xh)[t] = o;
}

// ---------------- preprocess: W transpose -> fp16 ----------------
__global__ __launch_bounds__(256) void convw_kernel(const float* __restrict__ Wz,
                                                    const float* __restrict__ Wh)
{
    __shared__ float tile[32][33];
    const int zz = blockIdx.z;
    const float* __restrict__ W = zz ? Wh : Wz;
    const int k0 = blockIdx.x * 32;
    const int n0 = blockIdx.y * 32;
    const int tx = threadIdx.x;
    const int ty = threadIdx.y;
    #pragma unroll
    for (int i = 0; i < 4; i++)
        tile[ty + 8 * i][tx] = W[(size_t)(k0 + ty + 8 * i) * 1024 + n0 + tx];
    __syncthreads();
    #pragma unroll
    for (int i = 0; i < 4; i++) {
        const int n = n0 + ty + 8 * i;
        g_Wt[(size_t)(zz * 1024 + n) * 1024 + k0 + tx] = __float2half_rn(tile[tx][ty + 8 * i]);
    }
}

// ---------------- HMMA dual GEMM (fp16 in, fp32 accum), 8 warps, fp16 out -------
#define BM 128
#define BN 256
#define NK 16
#define NSTAGE 4
#define A_BYTES (128 * 128)                 // 16 KB
#define B_BYTES (256 * 128)                 // 32 KB
#define STAGE_BYTES (A_BYTES + B_BYTES)     // 48 KB
#define OFF_BIAS (NSTAGE * STAGE_BYTES)     // 196608
#define GEMM_SMEM (OFF_BIAS + 1024)

__global__ __launch_bounds__(256, 1) void gemm_hmma_kernel(
    const float* __restrict__ bz, const float* __restrict__ bh)
{
    extern __shared__ char smem[];
    const uint32_t sb = smem_u32(smem);
    const int tid  = threadIdx.x;
    const int wid  = tid >> 5;
    const int lane = tid & 31;
    const int n0 = blockIdx.x * BN;
    const int m0 = blockIdx.y * BM;

    const bool isZ = (n0 < 1024);
    const int ncol = n0 & 1023;

    {
        const float* __restrict__ bias = isZ ? bz : bh;
        ((float*)(smem + OFF_BIAS))[tid] = bias[ncol + tid];
    }

    const int wm = wid & 1;
    const int wn = wid >> 1;

    const int a_row  = wm * 64 + (lane & 15);
    const uint32_t a_xor  = (uint32_t)((a_row & 7) << 4);
    const uint32_t a_half = (uint32_t)((lane >> 4) * 16);
    const int b_row  = wn * 64 + ((lane >> 3) & 1) * 8 + (lane & 7);
    const uint32_t b_xor  = (uint32_t)((b_row & 7) << 4);
    const uint32_t b_half = (uint32_t)((lane >> 4) * 16);

    float acc[4][8][4];
    #pragma unroll
    for (int i = 0; i < 4; i++)
        #pragma unroll
        for (int j = 0; j < 8; j++)
            #pragma unroll
            for (int q = 0; q < 4; q++) acc[i][j][q] = 0.0f;

    auto load_chunk = [&](int kc) {
        const uint32_t stb = sb + (uint32_t)((kc & (NSTAGE - 1)) * STAGE_BYTES);
        const int k0 = kc << 6;
        #pragma unroll
        for (int i = 0; i < 4; i++) {
            const int idx = tid + 256 * i;
            const int r = idx >> 3, g = idx & 7;
            const void* src = &g_Xh[(size_t)(m0 + r) * 1024 + k0 + g * 8];
            cp16(stb + (uint32_t)(r * 128 + ((g * 16) ^ ((r & 7) << 4))), src);
        }
        #pragma unroll
        for (int i = 0; i < 8; i++) {
            const int idx = tid + 256 * i;
            const int r = idx >> 3, g = idx & 7;
            const void* src = &g_Wt[(size_t)(n0 + r) * 1024 + k0 + g * 8];
            cp16(stb + A_BYTES + (uint32_t)(r * 128 + ((g * 16) ^ ((r & 7) << 4))), src);
        }
        asm volatile("cp.async.commit_group;" ::: "memory");
    };

    load_chunk(0);
    load_chunk(1);
    load_chunk(2);

    for (int kc = 0; kc < NK; kc++) {
        if (kc + 2 < NK)      asm volatile("cp.async.wait_group 2;" ::: "memory");
        else if (kc + 1 < NK) asm volatile("cp.async.wait_group 1;" ::: "memory");
        else                  asm volatile("cp.async.wait_group 0;" ::: "memory");
        __syncthreads();

        if (kc + 3 < NK) load_chunk(kc + 3);

        const uint32_t stb = sb + (uint32_t)((kc & (NSTAGE - 1)) * STAGE_BYTES);
        #pragma unroll
        for (int ks = 0; ks < 4; ks++) {
            uint32_t afr[4][4];
            uint32_t bfr[8][2];
            const uint32_t kbase = (uint32_t)(ks * 32);
            #pragma unroll
            for (int mt = 0; mt < 4; mt++) {
                const uint32_t addr = stb + (uint32_t)((a_row + mt * 16) * 128)
                                    + ((kbase + a_half) ^ a_xor);
                ldsm4(afr[mt], addr);
            }
            #pragma unroll
            for (int p = 0; p < 4; p++) {
                uint32_t r4[4];
                const uint32_t addr = stb + A_BYTES + (uint32_t)((b_row + p * 16) * 128)
                                    + ((kbase + b_half) ^ b_xor);
                ldsm4(r4, addr);
                bfr[2 * p + 0][0] = r4[0]; bfr[2 * p + 0][1] = r4[2];
                bfr[2 * p + 1][0] = r4[1]; bfr[2 * p + 1][1] = r4[3];
            }
            #pragma unroll
            for (int mt = 0; mt < 4; mt++)
                #pragma unroll
                for (int nt = 0; nt < 8; nt++)
                    mma_f16(acc[mt][nt], afr[mt], bfr[nt]);
        }
    }

    // epilogue: bias + fp16 store
    const float* sh_bias = (const float*)(smem + OFF_BIAS);
    __half* __restrict__ outp = isZ ? g_pz : g_ph;
    const int quad = lane >> 2;
    const int tq   = lane & 3;

    #pragma unroll
    for (int mt = 0; mt < 4; mt++) {
        const int row = m0 + wm * 64 + mt * 16 + quad;
        #pragma unroll
        for (int nt = 0; nt < 8; nt++) {
            const int cloc = wn * 64 + nt * 8 + tq * 2;
            const float b0 = sh_bias[cloc];
            const float b1 = sh_bias[cloc + 1];
            __half2 h01 = __floats2half2_rn(acc[mt][nt][0] + b0, acc[mt][nt][1] + b1);
            __half2 h23 = __floats2half2_rn(acc[mt][nt][2] + b0, acc[mt][nt][3] + b1);
            *(__half2*)(outp + (size_t)row * 1024 + ncol + cloc)       = h01;
            *(__half2*)(outp + (size_t)(row + 8) * 1024 + ncol + cloc) = h23;
        }
    }
}

// ---------------- chunked scan: pass 1 (2 d-lanes per thread) ----------------
__global__ __launch_bounds__(256) void scan_partial_kernel()
{
    const int g  = blockIdx.x * 256 + threadIdx.x;     // pair index
    const int dp = g & 511;                            // d-pair (d = 2*dp)
    const int bc = g >> 9;
    const int c  = bc & (NCHUNK - 1);
    const int b  = bc >> 6;

    const size_t base = ((size_t)(b * SEQT + c * CHUNK_LEN)) * DIM + dp * 2;
    float A0 = 1.0f, B0 = 0.0f, A1 = 1.0f, B1 = 0.0f;
    #pragma unroll 8
    for (int t = 0; t < CHUNK_LEN; t++) {
        const size_t idx = base + (size_t)t * DIM;
        const float2 zf = __half22float2(*(const __half2*)(g_pz + idx));
        const float2 hf = __half22float2(*(const __half2*)(g_ph + idx));
        const float s0 = sigmoid_tanh(zf.x);
        const float s1 = sigmoid_tanh(zf.y);
        const float a0 = 1.0f - s0;
        const float a1 = 1.0f - s1;
        B0 = fmaf(a0, B0, s0 * hf.x);  A0 *= a0;
        B1 = fmaf(a1, B1, s1 * hf.y);  A1 *= a1;
    }
    *(float2*)(g_Ag + bc * DIM + dp * 2) = make_float2(A0, A1);
    *(float2*)(g_Bg + bc * DIM + dp * 2) = make_float2(B0, B1);
}

// ---------------- chunked scan: pass 2 ----------------
__global__ __launch_bounds__(256) void scan_carry_kernel()
{
    const int g = blockIdx.x * 256 + threadIdx.x;
    const int d = g & (DIM - 1);
    const int b = g >> 10;

    float h = 0.0f;
    #pragma unroll
    for (int c = 0; c < NCHUNK; c++) {
        const int idx = (b * NCHUNK + c) * DIM + d;
        g_cr[idx] = h;
        h = fmaf(g_Ag[idx], h, g_Bg[idx]);
    }
}

// ---------------- fused scan pass 3 + Swish + LayerNorm (512 thr, 2 d/thread) ---
// Barrier-free recurrence (loads software-pipelined), then ONE reduction phase.
__global__ __launch_bounds__(512) void sfln_kernel(
    const float* __restrict__ beta_ptr,
    const float* __restrict__ gamma, const float* __restrict__ lbeta,
    float* __restrict__ out)
{
    __shared__ float2 red[CHUNK_LEN][16];   // [t][warp] = 4 KB
    __shared__ float2 tot[CHUNK_LEN];

    const int tid  = threadIdx.x;           // 0..511
    const int bc   = blockIdx.x;
    const int c    = bc & (NCHUNK - 1);
    const int b    = bc >> 6;
    const int lane = tid & 31;
    const int wrp  = tid >> 5;               // 0..15

    const int d0 = tid;
    const int d1 = tid + 512;

    const float beta = *beta_ptr;
    const size_t base = ((size_t)(b * SEQT + c * CHUNK_LEN)) * DIM;

    float h0 = g_cr[bc * DIM + d0];
    float h1 = g_cr[bc * DIM + d1];

    float y0[CHUNK_LEN], y1[CHUNK_LEN];

    // barrier-free recurrence: ptxas can batch the independent loads far ahead
    #pragma unroll
    for (int t = 0; t < CHUNK_LEN; t++) {
        const size_t idx = base + (size_t)t * DIM;
        const float z0  = __half2float(g_pz[idx + d0]);
        const float ht0 = __half2float(g_ph[idx + d0]);
        const float z1  = __half2float(g_pz[idx + d1]);
        const float ht1 = __half2float(g_ph[idx + d1]);
        const float s0 = sigmoid_tanh(z0);
        const float s1 = sigmoid_tanh(z1);
        h0 = fmaf(1.0f - s0, h0, s0 * ht0);
        h1 = fmaf(1.0f - s1, h1, s1 * ht1);
        const float sw0 = beta * h0;
        const float sw1 = beta * h1;
        y0[t] = sw0 * sigmoid_tanh(sw0);
        y1[t] = sw1 * sigmoid_tanh(sw1);
    }

    // stage 1: warp partials for every t
    #pragma unroll
    for (int t = 0; t < CHUNK_LEN; t++) {
        float s1v = y0[t] + y1[t];
        float s2v = fmaf(y0[t], y0[t], y1[t] * y1[t]);
        #pragma unroll
        for (int o = 16; o > 0; o >>= 1) {
            s1v += __shfl_xor_sync(0xffffffffu, s1v, o);
            s2v += __shfl_xor_sync(0xffffffffu, s2v, o);
        }
        if (lane == 0) red[t][wrp] = make_float2(s1v, s2v);
    }
    __syncthreads();

    // stage 2: warp w reduces t = 2w (lanes 0-15) and t = 2w+1 (lanes 16-31)
    {
        const int tt = 2 * wrp + (lane >> 4);
        float2 v = red[tt][lane & 15];
        #pragma unroll
        for (int o = 8; o > 0; o >>= 1) {
            v.x += __shfl_xor_sync(0xffffffffu, v.x, o);
            v.y += __shfl_xor_sync(0xffffffffu, v.y, o);
        }
        if ((lane & 15) == 0) tot[tt] = v;
    }
    __syncthreads();

    // normalize + store
    const float gm0 = gamma[d0], bt0 = lbeta[d0];
    const float gm1 = gamma[d1], bt1 = lbeta[d1];
    #pragma unroll
    for (int t = 0; t < CHUNK_LEN; t++) {
        const float2 T = tot[t];
        const float mu  = T.x * (1.0f / 1024.0f);
        const float var = fmaf(T.y, 1.0f / 1024.0f, -mu * mu);
        const float rs  = rsqrtf(var + 1e-5f);
        const size_t idx = base + (size_t)t * DIM;
        out[idx + d0] = (y0[t] - mu) * rs * gm0 + bt0;
        out[idx + d1] = (y1[t] - mu) * rs * gm1 + bt1;
    }
}

// ---------------- launch ----------------
extern "C" void kernel_launch(void* const* d_in, const int* in_sizes, int n_in,
                              void* d_out, int out_size)
{
    const float* x     = (const float*)d_in[0];
    const float* Wz    = (const float*)d_in[1];
    const float* bz    = (const float*)d_in[2];
    const float* Wh    = (const float*)d_in[3];
    const float* bh    = (const float*)d_in[4];
    const float* sbeta = (const float*)d_in[5];
    const float* gamma = (const float*)d_in[6];
    const float* lbeta = (const float*)d_in[7];
    float* out = (float*)d_out;

    convx_kernel<<<(M_TOT * DIM / 4) / 256, 256>>>(x);
    dim3 wgrid(32, 32, 2);
    convw_kernel<<<wgrid, dim3(32, 8)>>>(Wz, Wh);

    cudaFuncSetAttribute(gemm_hmma_kernel, cudaFuncAttributeMaxDynamicSharedMemorySize, GEMM_SMEM);
    gemm_hmma_kernel<<<dim3(2048 / BN, M_TOT / BM), 256, GEMM_SMEM>>>(bz, bh);

    scan_partial_kernel<<<(BATCH * NCHUNK * DIM / 2) / 256, 256>>>();
    scan_carry_kernel<<<(BATCH * DIM) / 256, 256>>>();
    sfln_kernel<<<BATCH * NCHUNK, 512>>>(sbeta, gamma, lbeta, out);
}